// round 5
// baseline (speedup 1.0000x reference)
#include <cuda_runtime.h>
#include <cuda_bf16.h>
#include <cstdint>

#define BB 64
#define TT 2048
#define EE 256
#define BT (BB*TT)
#define CHUNK 32
#define NCHUNK (TT/CHUNK)              // 64
#define NSCAN 8                        // scan blocks, 8 chains each
#define GATE_BLOCKS 128
#define TPB 512
#define FULLCNT 2048                   // 128 blocks * 16 warps per chunk

// xg time-major [T+pad][B] float4 (gates i,f,g,o; sigmoid gates pre-halved, bias folded)
__device__ float4 g_xg[(TT + 16) * BB];
// raw hidden states, time-major [T][B]
__device__ float  g_hs[TT * BB];
// producer->scan per-chunk counters (reset by last-finishing scan block)
__device__ int g_cnt[NCHUNK];
// scan->epilogue flags per (chunk, scan-block), padded to 32B (reset by sole consumer)
__device__ int g_sdone[NCHUNK * NSCAN * 8];
// scan completion rendezvous
__device__ int g_done;

__device__ __forceinline__ float tanha(float x) {
    float y; asm("tanh.approx.f32 %0, %1;" : "=f"(y) : "f"(x)); return y;
}
__device__ __forceinline__ int acq_ld(const int* p) {
    int v; asm volatile("ld.acquire.gpu.global.b32 %0, [%1];" : "=r"(v) : "l"(p) : "memory"); return v;
}
__device__ __forceinline__ void rel_add(int* p, int v) {
    asm volatile("red.release.gpu.global.add.s32 [%0], %1;" :: "l"(p), "r"(v) : "memory");
}
__device__ __forceinline__ float sigf(float h) {
    return fmaf(0.5f, tanha(0.5f * h), 0.5f);
}

__global__ __launch_bounds__(TPB, 1) void fused_kernel(
    const float* __restrict__ data,
    const int*   __restrict__ seq,
    const float* __restrict__ w_ih,
    const float* __restrict__ w_hh,
    const float* __restrict__ b_ih,
    const float* __restrict__ b_hh,
    float* __restrict__ out,
    int tail)
{
    const int tid  = threadIdx.x;
    const int warp = tid >> 5;
    const int lane = tid & 31;

    if (blockIdx.x < NSCAN) {
        // ================= SCAN BLOCKS (8 chains per block, lanes 0-7) =================
        if (tid >= 8) return;
        const int b  = blockIdx.x * 8 + tid;
        const float w0h = 0.5f * __ldg(w_hh+0);
        const float w1h = 0.5f * __ldg(w_hh+1);
        const float w2f =        __ldg(w_hh+2);
        const float w3h = 0.5f * __ldg(w_hh+3);
        const int   sb  = __ldg(seq + b);

        const float4* xp = g_xg + b;          // element t at xp[t*BB]
        float* hp = g_hs + b;

        int ready = 0;
        while (ready < 2) {
            if (acq_ld(g_cnt + ready) == FULLCNT) ready++;
        }

        float4 buf[8];
#pragma unroll
        for (int i = 0; i < 8; i++) buf[i] = __ldcg(xp + i * BB);

        float half_c = 0.f, tc = 0.f;
        float wo0 = 0.f, wo1 = 0.f, wo2 = 0.f, wo3 = 0.f;

        for (int ch = 0; ch < NCHUNK; ch++) {
            const int need = (ch + 2 < NCHUNK) ? (ch + 2) : NCHUNK;
            while (ready < need) {
                int far = ready + 6; if (far > NCHUNK-1) far = NCHUNK-1;
                if (acq_ld(g_cnt + far) == FULLCNT)        ready = far + 1;
                else if (acq_ld(g_cnt + ready) == FULLCNT) ready++;
            }
#pragma unroll
            for (int u = 0; u < CHUNK; u++) {
                const int t = ch * CHUNK + u;
                float4 x = buf[u & 7];
                buf[u & 7] = __ldcg(xp + (t + 8) * BB);   // padded: always in bounds

                // f gate first: it's on the c-chain; tanh issued right after its input
                float g1 = fmaf(wo1, tc, x.y);
                float t1 = tanha(g1);
                float g2 = fmaf(wo2, tc, x.z);
                float tg = tanha(g2);
                float g0 = fmaf(wo0, tc, x.x);
                float t0 = tanha(g0);
                float g3 = fmaf(wo3, tc, x.w);
                float t3 = tanha(g3);

                // c = f*c_prev + i*gg, f=0.5(1+t1), i=0.5(1+t0)
                float r   = fmaf(t1, half_c, half_c);
                float tgh = 0.5f * tg;
                float q   = fmaf(t0, tgh, tgh);
                float c   = r + q;
                half_c    = 0.5f * c;
                tc        = tanha(c);

                float o = fmaf(0.5f, t3, 0.5f);
                wo0 = w0h * o; wo1 = w1h * o; wo2 = w2f * o; wo3 = w3h * o;

                hp[t * BB] = o * tc;     // raw h; epilogue applies sigmoid+mask
            }
            __syncwarp(0xFFu);
            if (tid == 0) rel_add(&g_sdone[(ch * NSCAN + blockIdx.x) * 8], 1);
        }

        // tail: append seq_length as float if output carries the tuple
        if (b < tail) out[BT + b] = (float)sb;

        // last scan block resets producer counters for the next graph replay
        __syncwarp(0xFFu);
        if (tid == 0) {
            if (atomicAdd(&g_done, 1) == NSCAN - 1) {
#pragma unroll
                for (int i = 0; i < NCHUNK; i++) g_cnt[i] = 0;
                g_done = 0;
            }
        }
        return;
    }

    // ================= GATE + EPILOGUE BLOCKS (NSCAN .. NSCAN+127) =================
    const int kb = blockIdx.x - NSCAN;        // 0..127
    const int s  = kb * 16 + warp;            // 0..2047: task slot within each chunk
    const int bidx = s & 63;
    const int trow = s >> 6;                  // 0..31

    const float4* wv = reinterpret_cast<const float4*>(w_ih);
    float4 wr[8];
#pragma unroll
    for (int g = 0; g < 4; g++) {
        wr[2*g]   = __ldg(wv + g*64 + lane);
        wr[2*g+1] = __ldg(wv + g*64 + 32 + lane);
    }
    const float bb0 = __ldg(b_ih+0) + __ldg(b_hh+0);
    const float bb1 = __ldg(b_ih+1) + __ldg(b_hh+1);
    const float bb2 = __ldg(b_ih+2) + __ldg(b_hh+2);
    const float bb3 = __ldg(b_ih+3) + __ldg(b_hh+3);

    const float4* dpb = reinterpret_cast<const float4*>(data)
                      + ((size_t)bidx * TT + trow) * (EE/4);
    const int cstride = CHUNK * (EE/4);

    // depth-4 chunk prefetch pipeline
    float4 A0[4], A1[4];
#pragma unroll
    for (int p = 0; p < 4; p++) {
        A0[p] = __ldcs(dpb + p * cstride + lane);
        A1[p] = __ldcs(dpb + p * cstride + 32 + lane);
    }

#pragma unroll 4
    for (int c = 0; c < NCHUNK; c++) {
        const int slot = c & 3;
        float4 d0 = A0[slot], d1 = A1[slot];
        if (c + 4 < NCHUNK) {
            A0[slot] = __ldcs(dpb + (c + 4) * cstride + lane);
            A1[slot] = __ldcs(dpb + (c + 4) * cstride + 32 + lane);
        }

        float a0, a1, a2, a3;
        {
            float4 w0 = wr[0], w1 = wr[1];
            a0 = d0.x*w0.x; a0 = fmaf(d0.y,w0.y,a0); a0 = fmaf(d0.z,w0.z,a0); a0 = fmaf(d0.w,w0.w,a0);
            a0 = fmaf(d1.x,w1.x,a0); a0 = fmaf(d1.y,w1.y,a0); a0 = fmaf(d1.z,w1.z,a0); a0 = fmaf(d1.w,w1.w,a0);
        }
        {
            float4 w0 = wr[2], w1 = wr[3];
            a1 = d0.x*w0.x; a1 = fmaf(d0.y,w0.y,a1); a1 = fmaf(d0.z,w0.z,a1); a1 = fmaf(d0.w,w0.w,a1);
            a1 = fmaf(d1.x,w1.x,a1); a1 = fmaf(d1.y,w1.y,a1); a1 = fmaf(d1.z,w1.z,a1); a1 = fmaf(d1.w,w1.w,a1);
        }
        {
            float4 w0 = wr[4], w1 = wr[5];
            a2 = d0.x*w0.x; a2 = fmaf(d0.y,w0.y,a2); a2 = fmaf(d0.z,w0.z,a2); a2 = fmaf(d0.w,w0.w,a2);
            a2 = fmaf(d1.x,w1.x,a2); a2 = fmaf(d1.y,w1.y,a2); a2 = fmaf(d1.z,w1.z,a2); a2 = fmaf(d1.w,w1.w,a2);
        }
        {
            float4 w0 = wr[6], w1 = wr[7];
            a3 = d0.x*w0.x; a3 = fmaf(d0.y,w0.y,a3); a3 = fmaf(d0.z,w0.z,a3); a3 = fmaf(d0.w,w0.w,a3);
            a3 = fmaf(d1.x,w1.x,a3); a3 = fmaf(d1.y,w1.y,a3); a3 = fmaf(d1.z,w1.z,a3); a3 = fmaf(d1.w,w1.w,a3);
        }
#pragma unroll
        for (int off = 16; off > 0; off >>= 1) {
            a0 += __shfl_xor_sync(0xffffffffu, a0, off);
            a1 += __shfl_xor_sync(0xffffffffu, a1, off);
            a2 += __shfl_xor_sync(0xffffffffu, a2, off);
            a3 += __shfl_xor_sync(0xffffffffu, a3, off);
        }
        if (lane == 0) {
            const int t = c * CHUNK + trow;
            float4 v;
            v.x = 0.5f * (a0 + bb0);
            v.y = 0.5f * (a1 + bb1);
            v.z =         a2 + bb2;
            v.w = 0.5f * (a3 + bb3);
            g_xg[t * BB + bidx] = v;
        }
        __syncthreads();
        if (tid == 0) rel_add(&g_cnt[c], 16);
    }

    // -------- epilogue: one 32x32 (t,b) tile per block --------
    const int tch = kb >> 1;                   // scan chunk 0..63
    const int bh  = kb & 1;                    // b-half (scan blocks bh*4 .. bh*4+3)

    if (tid == 0) {
#pragma unroll
        for (int sb0 = 0; sb0 < 4; sb0++) {
            int* flag = &g_sdone[(tch * NSCAN + bh * 4 + sb0) * 8];
            unsigned ns = 256;
            while (acq_ld(flag) == 0) {
                __nanosleep(ns);
                if (ns < 4096) ns += ns;
            }
            *flag = 0;                         // sole consumer resets for next replay
        }
    }
    __syncthreads();

    __shared__ float tile[32][33];
    const int r = tid >> 5;                    // 0..15
    const int j = tid & 31;
    const int t0 = tch * 32, b0 = bh * 32;

    tile[r][j]      = __ldcg(&g_hs[(t0 + r)      * BB + b0 + j]);
    tile[r + 16][j] = __ldcg(&g_hs[(t0 + r + 16) * BB + b0 + j]);
    __syncthreads();

    {
        const int sb1 = __ldg(seq + b0 + r);
        float h = tile[j][r];
        out[(size_t)(b0 + r) * TT + t0 + j] = (t0 + j < sb1) ? sigf(h) : 0.5f;
    }
    {
        const int sb2 = __ldg(seq + b0 + r + 16);
        float h = tile[j][r + 16];
        out[(size_t)(b0 + r + 16) * TT + t0 + j] = (t0 + j < sb2) ? sigf(h) : 0.5f;
    }
}

extern "C" void kernel_launch(void* const* d_in, const int* in_sizes, int n_in,
                              void* d_out, int out_size)
{
    const float* data = (const float*)d_in[0];
    const int*   seq  = (const int*)  d_in[1];
    const float* w_ih = (const float*)d_in[2];
    const float* w_hh = (const float*)d_in[3];
    const float* b_ih = (const float*)d_in[4];
    const float* b_hh = (const float*)d_in[5];
    float* out = (float*)d_out;

    int tail = out_size - BT;
    if (tail < 0) tail = 0;
    if (tail > BB) tail = BB;

    fused_kernel<<<NSCAN + GATE_BLOCKS, TPB>>>(data, seq, w_ih, w_hh, b_ih, b_hh, out, tail);
}

// round 6
// speedup vs baseline: 1.4130x; 1.4130x over previous
#include <cuda_runtime.h>
#include <cuda_bf16.h>
#include <cstdint>

#define BB 64
#define TT 2048
#define EE 256
#define BT (BB*TT)
#define CHUNK 32
#define NCHUNK (TT/CHUNK)              // 64
#define NSCAN 8                        // scan blocks, 8 chains each
#define GATE_BLOCKS 128
#define TPB 512
#define FULLCNT 2048                   // 128 blocks * 16 warps per chunk

// xg time-major [T+pad][B] float4 (gates i,f,g,o; sigmoid gates pre-halved, bias folded)
__device__ float4 g_xg[(TT + 16) * BB];
// producer->scan per-chunk counters (reset by last-finishing scan block)
__device__ int g_cnt[NCHUNK];
// scan completion rendezvous
__device__ int g_done;

__device__ __forceinline__ float tanha(float x) {
    float y; asm("tanh.approx.f32 %0, %1;" : "=f"(y) : "f"(x)); return y;
}
__device__ __forceinline__ int acq_ld(const int* p) {
    int v; asm volatile("ld.acquire.gpu.global.b32 %0, [%1];" : "=r"(v) : "l"(p) : "memory"); return v;
}
__device__ __forceinline__ void rel_add(int* p, int v) {
    asm volatile("red.release.gpu.global.add.s32 [%0], %1;" :: "l"(p), "r"(v) : "memory");
}
__device__ __forceinline__ float sigf(float h) {
    return fmaf(0.5f, tanha(0.5f * h), 0.5f);
}

__global__ __launch_bounds__(TPB, 1) void fused_kernel(
    const float* __restrict__ data,
    const int*   __restrict__ seq,
    const float* __restrict__ w_ih,
    const float* __restrict__ w_hh,
    const float* __restrict__ b_ih,
    const float* __restrict__ b_hh,
    float* __restrict__ out,
    int tail)
{
    const int tid  = threadIdx.x;
    const int warp = tid >> 5;
    const int lane = tid & 31;

    if (blockIdx.x < NSCAN) {
        // ============ SCAN BLOCKS: warp0 = recurrence, warp1 = output ============
        if (warp >= 2) return;

        __shared__ float hbuf[2][8][33];   // [parity][chain][step] — conflict-free

        if (warp == 1) {
            // ---------------- consumer warp ----------------
            int sq[8];
#pragma unroll
            for (int b = 0; b < 8; b++) sq[b] = __ldg(seq + blockIdx.x * 8 + b);

            for (int ch = 0; ch < NCHUNK; ch++) {
                const int p = ch & 1;
                asm volatile("bar.sync %0, 64;" :: "r"(1 + p) : "memory");  // FULL_p
                const int t = ch * 32 + lane;
#pragma unroll
                for (int b = 0; b < 8; b++) {
                    float h = hbuf[p][b][lane];
                    float v = (t < sq[b]) ? sigf(h) : 0.5f;
                    out[(size_t)(blockIdx.x * 8 + b) * TT + t] = v;
                }
                if (ch + 2 < NCHUNK)
                    asm volatile("bar.arrive %0, 64;" :: "r"(3 + p) : "memory");  // FREE_p
            }
            // tail: append seq_length as float if output carries the tuple
            const int gb = blockIdx.x * 8 + lane;
            if (lane < 8 && gb < tail) out[BT + gb] = (float)sq[lane];
            return;
        }

        // ---------------- producer warp (lanes 0-7 = chains) ----------------
        const bool act = (lane < 8);
        const int bload = blockIdx.x * 8 + (act ? lane : 7);  // clamp: no extra traffic
        const float w0h = 0.5f * __ldg(w_hh+0);
        const float w1h = 0.5f * __ldg(w_hh+1);
        const float w2f =        __ldg(w_hh+2);
        const float w3h = 0.5f * __ldg(w_hh+3);

        const float4* xp = g_xg + bload;      // element t at xp[t*BB]

        int ready = 0;
        while (ready < 2) {
            if (acq_ld(g_cnt + ready) == FULLCNT) ready++;
        }

        float4 buf[8];
#pragma unroll
        for (int i = 0; i < 8; i++) buf[i] = __ldcg(xp + i * BB);

        float half_c = 0.f, tc = 0.f;
        float wo0 = 0.f, wo1 = 0.f, wo2 = 0.f, wo3 = 0.f;

        for (int ch = 0; ch < NCHUNK; ch++) {
            const int p = ch & 1;
            const int need = (ch + 2 < NCHUNK) ? (ch + 2) : NCHUNK;
            while (ready < need) {
                int far = ready + 6; if (far > NCHUNK-1) far = NCHUNK-1;
                if (acq_ld(g_cnt + far) == FULLCNT)        ready = far + 1;
                else if (acq_ld(g_cnt + ready) == FULLCNT) ready++;
            }
            if (ch >= 2)
                asm volatile("bar.sync %0, 64;" :: "r"(3 + p) : "memory");   // wait FREE_p

#pragma unroll
            for (int u = 0; u < CHUNK; u++) {
                const int t = ch * CHUNK + u;
                float4 x = buf[u & 7];
                buf[u & 7] = __ldcg(xp + (t + 8) * BB);   // padded: always in bounds

                // f gate first (on the c-chain), tanh right after its input
                float g1 = fmaf(wo1, tc, x.y);
                float t1 = tanha(g1);
                float g2 = fmaf(wo2, tc, x.z);
                float tg = tanha(g2);
                float g0 = fmaf(wo0, tc, x.x);
                float t0 = tanha(g0);
                float g3 = fmaf(wo3, tc, x.w);
                float t3 = tanha(g3);

                // c = f*c_prev + i*gg,  f=0.5(1+t1), i=0.5(1+t0)
                float r   = fmaf(t1, half_c, half_c);
                float tgh = 0.5f * tg;
                float q   = fmaf(t0, tgh, tgh);
                float c   = r + q;
                half_c    = 0.5f * c;
                tc        = tanha(c);

                float o = fmaf(0.5f, t3, 0.5f);
                wo0 = w0h * o; wo1 = w1h * o; wo2 = w2f * o; wo3 = w3h * o;

                if (act) hbuf[p][lane][u] = o * tc;   // raw h -> consumer warp
            }
            asm volatile("bar.arrive %0, 64;" :: "r"(1 + p) : "memory");     // FULL_p
        }

        // last scan block resets producer counters for the next graph replay
        __syncwarp();
        if (lane == 0) {
            if (atomicAdd(&g_done, 1) == NSCAN - 1) {
#pragma unroll
                for (int i = 0; i < NCHUNK; i++) g_cnt[i] = 0;
                g_done = 0;
            }
        }
        return;
    }

    // ================= GATE BLOCKS (NSCAN .. NSCAN+127) =================
    const int kb = blockIdx.x - NSCAN;        // 0..127
    const int s  = kb * 16 + warp;            // 0..2047: task slot within each chunk
    const int bidx = s & 63;
    const int trow = s >> 6;                  // 0..31

    const float4* wv = reinterpret_cast<const float4*>(w_ih);
    float4 wr[8];
#pragma unroll
    for (int g = 0; g < 4; g++) {
        wr[2*g]   = __ldg(wv + g*64 + lane);
        wr[2*g+1] = __ldg(wv + g*64 + 32 + lane);
    }
    const float bb0 = __ldg(b_ih+0) + __ldg(b_hh+0);
    const float bb1 = __ldg(b_ih+1) + __ldg(b_hh+1);
    const float bb2 = __ldg(b_ih+2) + __ldg(b_hh+2);
    const float bb3 = __ldg(b_ih+3) + __ldg(b_hh+3);

    const float4* dpb = reinterpret_cast<const float4*>(data)
                      + ((size_t)bidx * TT + trow) * (EE/4);
    const int cstride = CHUNK * (EE/4);

    // depth-4 chunk prefetch pipeline
    float4 A0[4], A1[4];
#pragma unroll
    for (int p = 0; p < 4; p++) {
        A0[p] = __ldcs(dpb + p * cstride + lane);
        A1[p] = __ldcs(dpb + p * cstride + 32 + lane);
    }

#pragma unroll 4
    for (int c = 0; c < NCHUNK; c++) {
        const int slot = c & 3;
        float4 d0 = A0[slot], d1 = A1[slot];
        if (c + 4 < NCHUNK) {
            A0[slot] = __ldcs(dpb + (c + 4) * cstride + lane);
            A1[slot] = __ldcs(dpb + (c + 4) * cstride + 32 + lane);
        }

        float a0, a1, a2, a3;
        {
            float4 w0 = wr[0], w1 = wr[1];
            a0 = d0.x*w0.x; a0 = fmaf(d0.y,w0.y,a0); a0 = fmaf(d0.z,w0.z,a0); a0 = fmaf(d0.w,w0.w,a0);
            a0 = fmaf(d1.x,w1.x,a0); a0 = fmaf(d1.y,w1.y,a0); a0 = fmaf(d1.z,w1.z,a0); a0 = fmaf(d1.w,w1.w,a0);
        }
        {
            float4 w0 = wr[2], w1 = wr[3];
            a1 = d0.x*w0.x; a1 = fmaf(d0.y,w0.y,a1); a1 = fmaf(d0.z,w0.z,a1); a1 = fmaf(d0.w,w0.w,a1);
            a1 = fmaf(d1.x,w1.x,a1); a1 = fmaf(d1.y,w1.y,a1); a1 = fmaf(d1.z,w1.z,a1); a1 = fmaf(d1.w,w1.w,a1);
        }
        {
            float4 w0 = wr[4], w1 = wr[5];
            a2 = d0.x*w0.x; a2 = fmaf(d0.y,w0.y,a2); a2 = fmaf(d0.z,w0.z,a2); a2 = fmaf(d0.w,w0.w,a2);
            a2 = fmaf(d1.x,w1.x,a2); a2 = fmaf(d1.y,w1.y,a2); a2 = fmaf(d1.z,w1.z,a2); a2 = fmaf(d1.w,w1.w,a2);
        }
        {
            float4 w0 = wr[6], w1 = wr[7];
            a3 = d0.x*w0.x; a3 = fmaf(d0.y,w0.y,a3); a3 = fmaf(d0.z,w0.z,a3); a3 = fmaf(d0.w,w0.w,a3);
            a3 = fmaf(d1.x,w1.x,a3); a3 = fmaf(d1.y,w1.y,a3); a3 = fmaf(d1.z,w1.z,a3); a3 = fmaf(d1.w,w1.w,a3);
        }
#pragma unroll
        for (int off = 16; off > 0; off >>= 1) {
            a0 += __shfl_xor_sync(0xffffffffu, a0, off);
            a1 += __shfl_xor_sync(0xffffffffu, a1, off);
            a2 += __shfl_xor_sync(0xffffffffu, a2, off);
            a3 += __shfl_xor_sync(0xffffffffu, a3, off);
        }
        if (lane == 0) {
            const int t = c * CHUNK + trow;
            float4 v;
            v.x = 0.5f * (a0 + bb0);
            v.y = 0.5f * (a1 + bb1);
            v.z =         a2 + bb2;
            v.w = 0.5f * (a3 + bb3);
            g_xg[t * BB + bidx] = v;
        }
        __syncthreads();
        if (tid == 0) rel_add(&g_cnt[c], 16);
    }
}

extern "C" void kernel_launch(void* const* d_in, const int* in_sizes, int n_in,
                              void* d_out, int out_size)
{
    const float* data = (const float*)d_in[0];
    const int*   seq  = (const int*)  d_in[1];
    const float* w_ih = (const float*)d_in[2];
    const float* w_hh = (const float*)d_in[3];
    const float* b_ih = (const float*)d_in[4];
    const float* b_hh = (const float*)d_in[5];
    float* out = (float*)d_out;

    int tail = out_size - BT;
    if (tail < 0) tail = 0;
    if (tail > BB) tail = BB;

    fused_kernel<<<NSCAN + GATE_BLOCKS, TPB>>>(data, seq, w_ih, w_hh, b_ih, b_hh, out, tail);
}

// round 7
// speedup vs baseline: 2.1609x; 1.5293x over previous
#include <cuda_runtime.h>
#include <cuda_bf16.h>
#include <cstdint>

#define BB 64
#define TT 2048
#define EE 256
#define BT (BB*TT)
#define CHUNK 32
#define NCHUNK (TT/CHUNK)              // 64
#define NSCAN 8                        // scan blocks, 8 chains each
#define GATE_BLOCKS 128
#define TPB 512
#define FULLCNT 2048                   // 128 blocks * 16 warps per chunk

// xg time-major [T+pad][B] float4 (gates i,f,g,o; sigmoid gates pre-halved, bias folded)
__device__ float4 g_xg[(TT + 16) * BB];
// producer->scan per-chunk counters (reset by last-finishing scan-loader warp)
__device__ int g_cnt[NCHUNK];
// scan completion rendezvous
__device__ int g_done;

__device__ __forceinline__ float tanha(float x) {
    float y; asm("tanh.approx.f32 %0, %1;" : "=f"(y) : "f"(x)); return y;
}
__device__ __forceinline__ int acq_ld(const int* p) {
    int v; asm volatile("ld.acquire.gpu.global.b32 %0, [%1];" : "=r"(v) : "l"(p) : "memory"); return v;
}
__device__ __forceinline__ void rel_add(int* p, int v) {
    asm volatile("red.release.gpu.global.add.s32 [%0], %1;" :: "l"(p), "r"(v) : "memory");
}
__device__ __forceinline__ float sigf(float h) {
    return fmaf(0.5f, tanha(0.5f * h), 0.5f);
}
// named barriers: 1,2 = h-full(parity); 3,4 = h-free; 5,6 = x-full; 7,8 = x-free
#define BARS(id) asm volatile("bar.sync %0, 64;"   :: "r"(id) : "memory")
#define BARA(id) asm volatile("bar.arrive %0, 64;" :: "r"(id) : "memory")

__global__ __launch_bounds__(TPB, 1) void fused_kernel(
    const float* __restrict__ data,
    const int*   __restrict__ seq,
    const float* __restrict__ w_ih,
    const float* __restrict__ w_hh,
    const float* __restrict__ b_ih,
    const float* __restrict__ b_hh,
    float* __restrict__ out,
    int tail)
{
    const int tid  = threadIdx.x;
    const int warp = tid >> 5;
    const int lane = tid & 31;

    if (blockIdx.x < NSCAN) {
        // ===== SCAN BLOCKS: warp0 = recurrence, warp1 = output, warp2 = x loader =====
        if (warp >= 3) return;

        __shared__ float  hbuf[2][8][33];        // [parity][chain][step]
        __shared__ float4 xbuf[2][CHUNK][8];     // [parity][step][chain]

        if (warp == 2) {
            // ---------------- loader warp: g_cnt polling + x staging ----------------
            const int urow = (lane >> 3) * 8;    // 0,8,16,24
            const int bcol = lane & 7;
            const float4* src = g_xg + blockIdx.x * 8 + bcol;

            int ready = 0;
            for (int ch = 0; ch < NCHUNK; ch++) {
                const int p = ch & 1;
                while (ready <= ch) {
                    int far = ready + 6; if (far > NCHUNK-1) far = NCHUNK-1;
                    if (acq_ld(g_cnt + far) == FULLCNT)        ready = far + 1;
                    else if (acq_ld(g_cnt + ready) == FULLCNT) ready++;
                }
                if (ch >= 2) BARS(7 + p);        // wait x-buffer p free
                float4 v[8];
#pragma unroll
                for (int j = 0; j < 8; j++)
                    v[j] = __ldcg(src + (ch * CHUNK + urow + j) * BB);
#pragma unroll
                for (int j = 0; j < 8; j++)
                    xbuf[p][urow + j][bcol] = v[j];
                BARA(5 + p);                     // x-buffer p full
            }
            // last loader resets producer counters for the next graph replay
            __syncwarp();
            if (lane == 0) {
                if (atomicAdd(&g_done, 1) == NSCAN - 1) {
#pragma unroll
                    for (int i = 0; i < NCHUNK; i++) g_cnt[i] = 0;
                    g_done = 0;
                }
            }
            return;
        }

        if (warp == 1) {
            // ---------------- consumer warp: sigmoid + mask + store ----------------
            int sq[8];
#pragma unroll
            for (int b = 0; b < 8; b++) sq[b] = __ldg(seq + blockIdx.x * 8 + b);

            for (int ch = 0; ch < NCHUNK; ch++) {
                const int p = ch & 1;
                BARS(1 + p);                     // h full
                const int t = ch * 32 + lane;
#pragma unroll
                for (int b = 0; b < 8; b++) {
                    float h = hbuf[p][b][lane];
                    float v = (t < sq[b]) ? sigf(h) : 0.5f;
                    out[(size_t)(blockIdx.x * 8 + b) * TT + t] = v;
                }
                if (ch + 2 < NCHUNK) BARA(3 + p); // h buffer free
            }
            const int gb = blockIdx.x * 8 + lane;
            if (lane < 8 && gb < tail) out[BT + gb] = (float)sq[lane];
            return;
        }

        // ---------------- producer warp (lanes 0-7 = chains) ----------------
        const bool act = (lane < 8);
        const int lane8 = lane & 7;
        const float w0h = 0.5f * __ldg(w_hh+0);
        const float w1h = 0.5f * __ldg(w_hh+1);
        const float w2f =        __ldg(w_hh+2);
        const float w3h = 0.5f * __ldg(w_hh+3);

        float half_c = 0.f, h = 0.f;

        BARS(5);                                 // x chunk 0 full
        float4 x = xbuf[0][0][lane8];

        for (int ch = 0; ch < NCHUNK; ch++) {
            const int p = ch & 1;
            if (ch >= 2) BARS(3 + p);            // h buffer p free

#pragma unroll
            for (int u = 0; u < CHUNK; u++) {
                float4 xn;
                if (u < CHUNK - 1) xn = xbuf[p][u + 1][lane8];

                // gates: g_k = w_k * h + x_k   (sigmoid gates pre-halved)
                float g1 = fmaf(w1h, h, x.y);
                float t1 = tanha(g1);
                float g2 = fmaf(w2f, h, x.z);
                float tg = tanha(g2);
                float g0 = fmaf(w0h, h, x.x);
                float t0 = tanha(g0);
                float g3 = fmaf(w3h, h, x.w);
                float t3 = tanha(g3);

                float r  = fmaf(t1, half_c, half_c);  // f * c_prev
                float qq = fmaf(t0, tg, tg);          // 2 * i * gg
                float c  = fmaf(0.5f, qq, r);
                half_c   = 0.5f * c;
                float o  = fmaf(0.5f, t3, 0.5f);      // off-chain (t3 before tc)
                float tc = tanha(c);
                h = o * tc;

                if (act) hbuf[p][lane][u] = h;
                x = xn;
            }
            BARA(1 + p);                          // h full
            BARA(7 + p);                          // x buffer p free
            if (ch < NCHUNK - 1) {
                BARS(5 + (p ^ 1));                // next x chunk full
                x = xbuf[p ^ 1][0][lane8];
            }
        }
        return;
    }

    // ================= GATE BLOCKS (NSCAN .. NSCAN+127) =================
    const int kb = blockIdx.x - NSCAN;        // 0..127
    const int s  = kb * 16 + warp;            // 0..2047: task slot within each chunk
    const int bidx = s & 63;
    const int trow = s >> 6;                  // 0..31

    const float4* wv = reinterpret_cast<const float4*>(w_ih);
    float4 wr[8];
#pragma unroll
    for (int g = 0; g < 4; g++) {
        wr[2*g]   = __ldg(wv + g*64 + lane);
        wr[2*g+1] = __ldg(wv + g*64 + 32 + lane);
    }
    const float bb0 = __ldg(b_ih+0) + __ldg(b_hh+0);
    const float bb1 = __ldg(b_ih+1) + __ldg(b_hh+1);
    const float bb2 = __ldg(b_ih+2) + __ldg(b_hh+2);
    const float bb3 = __ldg(b_ih+3) + __ldg(b_hh+3);

    const float4* dpb = reinterpret_cast<const float4*>(data)
                      + ((size_t)bidx * TT + trow) * (EE/4);
    const int cstride = CHUNK * (EE/4);

    // depth-4 chunk prefetch pipeline
    float4 A0[4], A1[4];
#pragma unroll
    for (int p = 0; p < 4; p++) {
        A0[p] = __ldcs(dpb + p * cstride + lane);
        A1[p] = __ldcs(dpb + p * cstride + 32 + lane);
    }

#pragma unroll 4
    for (int c = 0; c < NCHUNK; c++) {
        const int slot = c & 3;
        float4 d0 = A0[slot], d1 = A1[slot];
        if (c + 4 < NCHUNK) {
            A0[slot] = __ldcs(dpb + (c + 4) * cstride + lane);
            A1[slot] = __ldcs(dpb + (c + 4) * cstride + 32 + lane);
        }

        float a0, a1, a2, a3;
        {
            float4 w0 = wr[0], w1 = wr[1];
            a0 = d0.x*w0.x; a0 = fmaf(d0.y,w0.y,a0); a0 = fmaf(d0.z,w0.z,a0); a0 = fmaf(d0.w,w0.w,a0);
            a0 = fmaf(d1.x,w1.x,a0); a0 = fmaf(d1.y,w1.y,a0); a0 = fmaf(d1.z,w1.z,a0); a0 = fmaf(d1.w,w1.w,a0);
        }
        {
            float4 w0 = wr[2], w1 = wr[3];
            a1 = d0.x*w0.x; a1 = fmaf(d0.y,w0.y,a1); a1 = fmaf(d0.z,w0.z,a1); a1 = fmaf(d0.w,w0.w,a1);
            a1 = fmaf(d1.x,w1.x,a1); a1 = fmaf(d1.y,w1.y,a1); a1 = fmaf(d1.z,w1.z,a1); a1 = fmaf(d1.w,w1.w,a1);
        }
        {
            float4 w0 = wr[4], w1 = wr[5];
            a2 = d0.x*w0.x; a2 = fmaf(d0.y,w0.y,a2); a2 = fmaf(d0.z,w0.z,a2); a2 = fmaf(d0.w,w0.w,a2);
            a2 = fmaf(d1.x,w1.x,a2); a2 = fmaf(d1.y,w1.y,a2); a2 = fmaf(d1.z,w1.z,a2); a2 = fmaf(d1.w,w1.w,a2);
        }
        {
            float4 w0 = wr[6], w1 = wr[7];
            a3 = d0.x*w0.x; a3 = fmaf(d0.y,w0.y,a3); a3 = fmaf(d0.z,w0.z,a3); a3 = fmaf(d0.w,w0.w,a3);
            a3 = fmaf(d1.x,w1.x,a3); a3 = fmaf(d1.y,w1.y,a3); a3 = fmaf(d1.z,w1.z,a3); a3 = fmaf(d1.w,w1.w,a3);
        }
#pragma unroll
        for (int off = 16; off > 0; off >>= 1) {
            a0 += __shfl_xor_sync(0xffffffffu, a0, off);
            a1 += __shfl_xor_sync(0xffffffffu, a1, off);
            a2 += __shfl_xor_sync(0xffffffffu, a2, off);
            a3 += __shfl_xor_sync(0xffffffffu, a3, off);
        }
        if (lane == 0) {
            const int t = c * CHUNK + trow;
            float4 v;
            v.x = 0.5f * (a0 + bb0);
            v.y = 0.5f * (a1 + bb1);
            v.z =         a2 + bb2;
            v.w = 0.5f * (a3 + bb3);
            g_xg[t * BB + bidx] = v;
        }
        __syncthreads();
        if (tid == 0) rel_add(&g_cnt[c], 16);
    }
}

extern "C" void kernel_launch(void* const* d_in, const int* in_sizes, int n_in,
                              void* d_out, int out_size)
{
    const float* data = (const float*)d_in[0];
    const int*   seq  = (const int*)  d_in[1];
    const float* w_ih = (const float*)d_in[2];
    const float* w_hh = (const float*)d_in[3];
    const float* b_ih = (const float*)d_in[4];
    const float* b_hh = (const float*)d_in[5];
    float* out = (float*)d_out;

    int tail = out_size - BT;
    if (tail < 0) tail = 0;
    if (tail > BB) tail = BB;

    fused_kernel<<<NSCAN + GATE_BLOCKS, TPB>>>(data, seq, w_ih, w_hh, b_ih, b_hh, out, tail);
}

// round 8
// speedup vs baseline: 2.2205x; 1.0276x over previous
#include <cuda_runtime.h>
#include <cuda_bf16.h>
#include <cstdint>

#define BB 64
#define TT 2048
#define EE 256
#define BT (BB*TT)
#define CHUNK 32
#define NCHUNK (TT/CHUNK)              // 64
#define NSCAN 8                        // scan blocks, 8 chains each
#define GATE_BLOCKS 128
#define TPB 512
#define FULLCNT 2048                   // 128 blocks * 16 warps per chunk

// Per-(t,b,gate) cubic Taylor coefficients (k0,k1,k2,k3) of gate(h_prev).
// Layout: [t][b][gate] float4.
__device__ float4 g_k[TT * BB * 4 + 64];
// producer->scan per-chunk counters (reset by last-finishing loader warp)
__device__ int g_cnt[NCHUNK];
// scan completion rendezvous
__device__ int g_done;

__device__ __forceinline__ float tanha(float x) {
    float y; asm("tanh.approx.f32 %0, %1;" : "=f"(y) : "f"(x)); return y;
}
__device__ __forceinline__ int acq_ld(const int* p) {
    int v; asm volatile("ld.acquire.gpu.global.b32 %0, [%1];" : "=r"(v) : "l"(p) : "memory"); return v;
}
__device__ __forceinline__ void rel_add(int* p, int v) {
    asm volatile("red.release.gpu.global.add.s32 [%0], %1;" :: "l"(p), "r"(v) : "memory");
}
__device__ __forceinline__ float sigf(float h) {
    return fmaf(0.5f, tanha(0.5f * h), 0.5f);
}
// named barriers: 1,2 = h-full(parity); 3,4 = h-free; 5,6 = x-full; 7,8 = x-free
#define BARS(id) asm volatile("bar.sync %0, 64;"   :: "r"(id) : "memory")
#define BARA(id) asm volatile("bar.arrive %0, 64;" :: "r"(id) : "memory")

__global__ __launch_bounds__(TPB, 1) void fused_kernel(
    const float* __restrict__ data,
    const int*   __restrict__ seq,
    const float* __restrict__ w_ih,
    const float* __restrict__ w_hh,
    const float* __restrict__ b_ih,
    const float* __restrict__ b_hh,
    float* __restrict__ out,
    int tail)
{
    const int tid  = threadIdx.x;
    const int warp = tid >> 5;
    const int lane = tid & 31;

    if (blockIdx.x < NSCAN) {
        // ===== SCAN BLOCKS: warp0 = recurrence, warp1 = output, warp2 = K loader =====
        if (warp >= 3) return;

        __shared__ float  hbuf[2][8][33];          // [parity][chain][step]
        __shared__ float4 xbuf[2][CHUNK][4][8];    // [parity][step][gate][chain]

        if (warp == 2) {
            // ---------- loader warp: g_cnt polling + coefficient staging ----------
            const int bsub = lane >> 2;            // chain 0..7
            const int gsub = lane & 3;             // gate 0..3
            const float4* src = g_k + ((size_t)(blockIdx.x * 8 + bsub)) * 4 + gsub;

            int ready = 0;
            for (int ch = 0; ch < NCHUNK; ch++) {
                const int p = ch & 1;
                while (ready <= ch) {
                    int far = ready + 6; if (far > NCHUNK-1) far = NCHUNK-1;
                    if (acq_ld(g_cnt + far) == FULLCNT)        ready = far + 1;
                    else if (acq_ld(g_cnt + ready) == FULLCNT) ready++;
                }
                if (ch >= 2) BARS(7 + p);          // wait x-buffer p free
#pragma unroll
                for (int uu = 0; uu < CHUNK; uu += 8) {
                    float4 v[8];
#pragma unroll
                    for (int j = 0; j < 8; j++)
                        v[j] = __ldcg(src + (size_t)(ch * CHUNK + uu + j) * (BB * 4));
#pragma unroll
                    for (int j = 0; j < 8; j++)
                        xbuf[p][uu + j][gsub][bsub] = v[j];
                }
                BARA(5 + p);                       // x-buffer p full
            }
            // last loader resets producer counters for the next graph replay
            __syncwarp();
            if (lane == 0) {
                if (atomicAdd(&g_done, 1) == NSCAN - 1) {
#pragma unroll
                    for (int i = 0; i < NCHUNK; i++) g_cnt[i] = 0;
                    g_done = 0;
                }
            }
            return;
        }

        if (warp == 1) {
            // ---------------- consumer warp: sigmoid + mask + store ----------------
            int sq[8];
#pragma unroll
            for (int b = 0; b < 8; b++) sq[b] = __ldg(seq + blockIdx.x * 8 + b);

            for (int ch = 0; ch < NCHUNK; ch++) {
                const int p = ch & 1;
                BARS(1 + p);                       // h full
                const int t = ch * 32 + lane;
#pragma unroll
                for (int b = 0; b < 8; b++) {
                    float h = hbuf[p][b][lane];
                    float v = (t < sq[b]) ? sigf(h) : 0.5f;
                    out[(size_t)(blockIdx.x * 8 + b) * TT + t] = v;
                }
                if (ch + 2 < NCHUNK) BARA(3 + p);  // h buffer free
            }
            const int gb = blockIdx.x * 8 + lane;
            if (lane < 8 && gb < tail) out[BT + gb] = (float)sq[lane];
            return;
        }

        // ---------------- producer warp (lanes 0-7 = chains) ----------------
        const bool act = (lane < 8);
        const int l8 = lane & 7;

        float c = 0.f, h = 0.f;

        BARS(5);                                   // x chunk 0 full
        float4 Ki = xbuf[0][0][0][l8];
        float4 Kf = xbuf[0][0][1][l8];
        float4 Kg = xbuf[0][0][2][l8];
        float4 Ko = xbuf[0][0][3][l8];

        for (int ch = 0; ch < NCHUNK; ch++) {
            const int p = ch & 1;
            if (ch >= 2) BARS(3 + p);              // h buffer p free

#pragma unroll
            for (int u = 0; u < CHUNK; u++) {
                float4 ni, nf, ng, no;
                if (u < CHUNK - 1) {
                    ni = xbuf[p][u + 1][0][l8];
                    nf = xbuf[p][u + 1][1][l8];
                    ng = xbuf[p][u + 1][2][l8];
                    no = xbuf[p][u + 1][3][l8];
                }
                // Estrin cubic: phi = (k0 + k1 h) + h^2 (k2 + k3 h)
                float h2  = h * h;
                float pf1 = fmaf(Kf.y, h, Kf.x), pf2 = fmaf(Kf.w, h, Kf.z);
                float pi1 = fmaf(Ki.y, h, Ki.x), pi2 = fmaf(Ki.w, h, Ki.z);
                float pg1 = fmaf(Kg.y, h, Kg.x), pg2 = fmaf(Kg.w, h, Kg.z);
                float po1 = fmaf(Ko.y, h, Ko.x), po2 = fmaf(Ko.w, h, Ko.z);
                float fv = fmaf(h2, pf2, pf1);
                float iv = fmaf(h2, pi2, pi1);
                float gv = fmaf(h2, pg2, pg1);
                float ov = fmaf(h2, po2, po1);

                float ig = iv * gv;
                c = fmaf(fv, c, ig);
                float tc = tanha(c);
                h = ov * tc;

                if (act) hbuf[p][lane][u] = h;
                Ki = ni; Kf = nf; Kg = ng; Ko = no;
            }
            BARA(1 + p);                           // h full
            BARA(7 + p);                           // x buffer p free
            if (ch < NCHUNK - 1) {
                BARS(5 + (p ^ 1));                 // next x chunk full
                Ki = xbuf[p ^ 1][0][0][l8];
                Kf = xbuf[p ^ 1][0][1][l8];
                Kg = xbuf[p ^ 1][0][2][l8];
                Ko = xbuf[p ^ 1][0][3][l8];
            }
        }
        return;
    }

    // ================= GATE BLOCKS (NSCAN .. NSCAN+127) =================
    const int kb = blockIdx.x - NSCAN;        // 0..127
    const int s  = kb * 16 + warp;            // 0..2047: task slot within each chunk
    const int bidx = s & 63;
    const int trow = s >> 6;                  // 0..31

    const float4* wv = reinterpret_cast<const float4*>(w_ih);
    float4 wr[8];
#pragma unroll
    for (int g = 0; g < 4; g++) {
        wr[2*g]   = __ldg(wv + g*64 + lane);
        wr[2*g+1] = __ldg(wv + g*64 + 32 + lane);
    }
    const float bb0 = __ldg(b_ih+0) + __ldg(b_hh+0);
    const float bb1 = __ldg(b_ih+1) + __ldg(b_hh+1);
    const float bb2 = __ldg(b_ih+2) + __ldg(b_hh+2);
    const float bb3 = __ldg(b_ih+3) + __ldg(b_hh+3);
    const float wsel = __ldg(w_hh + (lane & 3));   // recurrent weight for this lane's gate

    const float4* dpb = reinterpret_cast<const float4*>(data)
                      + ((size_t)bidx * TT + trow) * (EE/4);
    const int cstride = CHUNK * (EE/4);

    // depth-4 chunk prefetch pipeline
    float4 A0[4], A1[4];
#pragma unroll
    for (int p = 0; p < 4; p++) {
        A0[p] = __ldcs(dpb + p * cstride + lane);
        A1[p] = __ldcs(dpb + p * cstride + 32 + lane);
    }

#pragma unroll 4
    for (int c = 0; c < NCHUNK; c++) {
        const int slot = c & 3;
        float4 d0 = A0[slot], d1 = A1[slot];
        if (c + 4 < NCHUNK) {
            A0[slot] = __ldcs(dpb + (c + 4) * cstride + lane);
            A1[slot] = __ldcs(dpb + (c + 4) * cstride + 32 + lane);
        }

        float a0, a1, a2, a3;
        {
            float4 w0 = wr[0], w1 = wr[1];
            a0 = d0.x*w0.x; a0 = fmaf(d0.y,w0.y,a0); a0 = fmaf(d0.z,w0.z,a0); a0 = fmaf(d0.w,w0.w,a0);
            a0 = fmaf(d1.x,w1.x,a0); a0 = fmaf(d1.y,w1.y,a0); a0 = fmaf(d1.z,w1.z,a0); a0 = fmaf(d1.w,w1.w,a0);
        }
        {
            float4 w0 = wr[2], w1 = wr[3];
            a1 = d0.x*w0.x; a1 = fmaf(d0.y,w0.y,a1); a1 = fmaf(d0.z,w0.z,a1); a1 = fmaf(d0.w,w0.w,a1);
            a1 = fmaf(d1.x,w1.x,a1); a1 = fmaf(d1.y,w1.y,a1); a1 = fmaf(d1.z,w1.z,a1); a1 = fmaf(d1.w,w1.w,a1);
        }
        {
            float4 w0 = wr[4], w1 = wr[5];
            a2 = d0.x*w0.x; a2 = fmaf(d0.y,w0.y,a2); a2 = fmaf(d0.z,w0.z,a2); a2 = fmaf(d0.w,w0.w,a2);
            a2 = fmaf(d1.x,w1.x,a2); a2 = fmaf(d1.y,w1.y,a2); a2 = fmaf(d1.z,w1.z,a2); a2 = fmaf(d1.w,w1.w,a2);
        }
        {
            float4 w0 = wr[6], w1 = wr[7];
            a3 = d0.x*w0.x; a3 = fmaf(d0.y,w0.y,a3); a3 = fmaf(d0.z,w0.z,a3); a3 = fmaf(d0.w,w0.w,a3);
            a3 = fmaf(d1.x,w1.x,a3); a3 = fmaf(d1.y,w1.y,a3); a3 = fmaf(d1.z,w1.z,a3); a3 = fmaf(d1.w,w1.w,a3);
        }
#pragma unroll
        for (int off = 16; off > 0; off >>= 1) {
            a0 += __shfl_xor_sync(0xffffffffu, a0, off);
            a1 += __shfl_xor_sync(0xffffffffu, a1, off);
            a2 += __shfl_xor_sync(0xffffffffu, a2, off);
            a3 += __shfl_xor_sync(0xffffffffu, a3, off);
        }
        // lanes 0-3: cubic Taylor coefficients of gate (lane) around x = a + bias
        if (lane < 4) {
            float a = (lane == 0) ? a0 + bb0
                    : (lane == 1) ? a1 + bb1
                    : (lane == 2) ? a2 + bb2
                    :               a3 + bb3;
            float w  = wsel;
            float w2 = w * w;
            float w3 = w2 * w;
            float4 K;
            if (lane == 2) {
                // tanh gate
                float T  = tanha(a);
                float T1 = fmaf(-T, T, 1.0f);                 // 1 - T^2
                K.x = T;
                K.y = T1 * w;
                K.z = -T * T1 * w2;                           // T''/2 * w^2
                K.w = T1 * fmaf(T, T, -0.3333333333f) * w3;   // T'''/6 * w^3
            } else {
                // sigmoid gate
                float ss = fmaf(0.5f, tanha(0.5f * a), 0.5f);
                float s1 = ss - ss * ss;                      // s(1-s)
                K.x = ss;
                K.y = s1 * w;
                K.z = s1 * (0.5f - ss) * w2;                  // s''/2 * w^2
                K.w = s1 * (fmaf(ss, ss, -ss) + 0.1666666667f) * w3;  // s'''/6 * w^3
            }
            const int t = c * CHUNK + trow;
            g_k[((size_t)t * BB + bidx) * 4 + lane] = K;
        }
        __syncthreads();
        if (tid == 0) rel_add(&g_cnt[c], 16);
    }
}

extern "C" void kernel_launch(void* const* d_in, const int* in_sizes, int n_in,
                              void* d_out, int out_size)
{
    const float* data = (const float*)d_in[0];
    const int*   seq  = (const int*)  d_in[1];
    const float* w_ih = (const float*)d_in[2];
    const float* w_hh = (const float*)d_in[3];
    const float* b_ih = (const float*)d_in[4];
    const float* b_hh = (const float*)d_in[5];
    float* out = (float*)d_out;

    int tail = out_size - BT;
    if (tail < 0) tail = 0;
    if (tail > BB) tail = BB;

    fused_kernel<<<NSCAN + GATE_BLOCKS, TPB>>>(data, seq, w_ih, w_hh, b_ih, b_hh, out, tail);
}

// round 9
// speedup vs baseline: 2.8500x; 1.2835x over previous
#include <cuda_runtime.h>
#include <cuda_bf16.h>
#include <cstdint>

#define BB 64
#define TT 2048
#define EE 256
#define BT (BB*TT)
#define CHUNK 32
#define NCHUNK (TT/CHUNK)              // 64
#define NSEG 16                        // scan segments (blocks 0..15)
#define SEGLEN 128
#define GATE_BLOCKS 128
#define TPB 512
#define FULLCNT 2048                   // 128 blocks * 16 warps per chunk

// xg time-major [T+pad][B] float4 (gates i,f,g,o; sigmoid gates pre-halved, bias folded)
__device__ float4 g_xg[(TT + 16) * BB];
// producer->scan per-chunk counters (reset by last-finishing poller)
__device__ int g_cnt[NCHUNK];
// poller completion rendezvous
__device__ int g_done;

__device__ __forceinline__ float tanha(float x) {
    float y; asm("tanh.approx.f32 %0, %1;" : "=f"(y) : "f"(x)); return y;
}
__device__ __forceinline__ int acq_ld(const int* p) {
    int v; asm volatile("ld.acquire.gpu.global.b32 %0, [%1];" : "=r"(v) : "l"(p) : "memory"); return v;
}
__device__ __forceinline__ void rel_add(int* p, int v) {
    asm volatile("red.release.gpu.global.add.s32 [%0], %1;" :: "l"(p), "r"(v) : "memory");
}
__device__ __forceinline__ int atom_aa(int* p, int v) {
    int o; asm volatile("atom.acq_rel.gpu.global.add.s32 %0, [%1], %2;"
                        : "=r"(o) : "l"(p), "r"(v) : "memory"); return o;
}
__device__ __forceinline__ float sigf(float h) {
    return fmaf(0.5f, tanha(0.5f * h), 0.5f);
}
// named barriers, 96 participants (3 warps). 1=XRDY, 2/3=HFULL(par), 4/5=HFREE(par)
#define BARS96(id) asm volatile("bar.sync %0, 96;"   :: "r"(id) : "memory")
#define BARA96(id) asm volatile("bar.arrive %0, 96;" :: "r"(id) : "memory")

__global__ __launch_bounds__(TPB, 1) void fused_kernel(
    const float* __restrict__ data,
    const int*   __restrict__ seq,
    const float* __restrict__ w_ih,
    const float* __restrict__ w_hh,
    const float* __restrict__ b_ih,
    const float* __restrict__ b_hh,
    float* __restrict__ out,
    int tail)
{
    const int tid  = threadIdx.x;
    const int warp = tid >> 5;
    const int lane = tid & 31;

    if (blockIdx.x < NSEG) {
        // ========== SCAN BLOCK for segment s: warm-up 128 + real 128 steps ==========
        const int s  = blockIdx.x;
        const int tw = (s == 0) ? 0 : s * SEGLEN - SEGLEN;   // first (warm) step
        const int nchunks = (s == 0) ? 4 : 8;
        const int warmch  = nchunks - 4;
        const int gk0 = tw >> 5;                             // first global chunk

        __shared__ float hbuf[2][BB][33];                    // [parity][chain][step]

        if (warp >= 4) return;

        if (warp == 2) {
            // ---------------- poller warp ----------------
            int ready = 0;
            for (int k = 0; k < nchunks; k++) {
                int need = gk0 + k + 2; if (need > NCHUNK) need = NCHUNK;
                while (ready < need) {
                    int far = ready + 6; if (far > NCHUNK-1) far = NCHUNK-1;
                    if (acq_ld(g_cnt + far) == FULLCNT)        ready = far + 1;
                    else if (acq_ld(g_cnt + ready) == FULLCNT) ready++;
                }
                BARS96(1);                                   // XRDY for chunk k
            }
            __syncwarp();
            if (lane == 0) {
                if (atom_aa(&g_done, 1) == NSEG - 1) {       // last poller: reset
#pragma unroll
                    for (int i = 0; i < NCHUNK; i++) g_cnt[i] = 0;
                    g_done = 0;
                }
            }
            return;
        }

        if (warp == 3) {
            // ---------------- consumer warp: sigmoid + mask + store ----------------
            for (int rc = 0; rc < 4; rc++) {
                const int p = rc & 1;
                BARS96(2 + p);                               // HFULL
                const int tcol = s * SEGLEN + rc * 32 + lane;
#pragma unroll 4
                for (int b = 0; b < BB; b++) {
                    float h = hbuf[p][b][lane];
                    int sq = __ldg(seq + b);
                    float v = (tcol < sq) ? sigf(h) : 0.5f;
                    out[(size_t)b * TT + tcol] = v;
                }
                if (rc < 2) BARA96(4 + p);                   // HFREE
            }
            if (s == 0) {                                    // tuple tail: seq as float
                if (lane      < tail) out[BT + lane]      = (float)__ldg(seq + lane);
                if (lane + 32 < tail) out[BT + lane + 32] = (float)__ldg(seq + lane + 32);
            }
            return;
        }

        // ---------------- scan warps 0,1: chains warp*32 + lane ----------------
        const int b = warp * 32 + lane;
        const float w0h = 0.5f * __ldg(w_hh+0);
        const float w1h = 0.5f * __ldg(w_hh+1);
        const float w2f =        __ldg(w_hh+2);
        const float w3h = 0.5f * __ldg(w_hh+3);

        const float4* xp = g_xg + b;                         // element t at xp[t*BB]

        float4 buf[8];
        float half_c = 0.f, h = 0.f;
        int t = tw;

        for (int k = 0; k < nchunks; k++) {
            BARS96(1);                                       // XRDY: chunks <= gk0+k+1 done
            if (k == 0) {
#pragma unroll
                for (int i = 0; i < 8; i++) buf[i] = __ldcg(xp + (tw + i) * BB);
            }
            const bool real = (k >= warmch);
            const int rc = k - warmch;
            const int p = rc & 1;
            if (real && rc >= 2) BARS96(4 + p);              // HFREE before reuse

#pragma unroll
            for (int u = 0; u < CHUNK; u++) {
                float4 x = buf[u & 7];
                buf[u & 7] = __ldcg(xp + (t + u + 8) * BB);  // padded: in bounds

                float g1 = fmaf(w1h, h, x.y);
                float t1 = tanha(g1);
                float g2 = fmaf(w2f, h, x.z);
                float tg = tanha(g2);
                float g0 = fmaf(w0h, h, x.x);
                float t0 = tanha(g0);
                float g3 = fmaf(w3h, h, x.w);
                float t3 = tanha(g3);

                float r  = fmaf(t1, half_c, half_c);         // f * c_prev
                float qq = fmaf(t0, tg, tg);                 // 2 i g
                float c  = fmaf(0.5f, qq, r);
                half_c   = 0.5f * c;
                float o  = fmaf(0.5f, t3, 0.5f);
                float tc = tanha(c);
                h = o * tc;

                if (real) hbuf[p][b][u] = h;
            }
            t += CHUNK;
            if (real) BARA96(2 + p);                         // HFULL
        }
        return;
    }

    // ================= GATE BLOCKS (NSEG .. NSEG+127) =================
    const int kb = blockIdx.x - NSEG;         // 0..127
    const int s  = kb * 16 + warp;            // 0..2047: task slot within each chunk
    const int bidx = s & 63;
    const int trow = s >> 6;                  // 0..31

    const float4* wv = reinterpret_cast<const float4*>(w_ih);
    float4 wr[8];
#pragma unroll
    for (int g = 0; g < 4; g++) {
        wr[2*g]   = __ldg(wv + g*64 + lane);
        wr[2*g+1] = __ldg(wv + g*64 + 32 + lane);
    }
    const float bb0 = __ldg(b_ih+0) + __ldg(b_hh+0);
    const float bb1 = __ldg(b_ih+1) + __ldg(b_hh+1);
    const float bb2 = __ldg(b_ih+2) + __ldg(b_hh+2);
    const float bb3 = __ldg(b_ih+3) + __ldg(b_hh+3);

    const float4* dpb = reinterpret_cast<const float4*>(data)
                      + ((size_t)bidx * TT + trow) * (EE/4);
    const int cstride = CHUNK * (EE/4);

    // depth-4 chunk prefetch pipeline
    float4 A0[4], A1[4];
#pragma unroll
    for (int p = 0; p < 4; p++) {
        A0[p] = __ldcs(dpb + p * cstride + lane);
        A1[p] = __ldcs(dpb + p * cstride + 32 + lane);
    }

#pragma unroll 4
    for (int c = 0; c < NCHUNK; c++) {
        const int slot = c & 3;
        float4 d0 = A0[slot], d1 = A1[slot];
        if (c + 4 < NCHUNK) {
            A0[slot] = __ldcs(dpb + (c + 4) * cstride + lane);
            A1[slot] = __ldcs(dpb + (c + 4) * cstride + 32 + lane);
        }

        float a0, a1, a2, a3;
        {
            float4 w0 = wr[0], w1 = wr[1];
            a0 = d0.x*w0.x; a0 = fmaf(d0.y,w0.y,a0); a0 = fmaf(d0.z,w0.z,a0); a0 = fmaf(d0.w,w0.w,a0);
            a0 = fmaf(d1.x,w1.x,a0); a0 = fmaf(d1.y,w1.y,a0); a0 = fmaf(d1.z,w1.z,a0); a0 = fmaf(d1.w,w1.w,a0);
        }
        {
            float4 w0 = wr[2], w1 = wr[3];
            a1 = d0.x*w0.x; a1 = fmaf(d0.y,w0.y,a1); a1 = fmaf(d0.z,w0.z,a1); a1 = fmaf(d0.w,w0.w,a1);
            a1 = fmaf(d1.x,w1.x,a1); a1 = fmaf(d1.y,w1.y,a1); a1 = fmaf(d1.z,w1.z,a1); a1 = fmaf(d1.w,w1.w,a1);
        }
        {
            float4 w0 = wr[4], w1 = wr[5];
            a2 = d0.x*w0.x; a2 = fmaf(d0.y,w0.y,a2); a2 = fmaf(d0.z,w0.z,a2); a2 = fmaf(d0.w,w0.w,a2);
            a2 = fmaf(d1.x,w1.x,a2); a2 = fmaf(d1.y,w1.y,a2); a2 = fmaf(d1.z,w1.z,a2); a2 = fmaf(d1.w,w1.w,a2);
        }
        {
            float4 w0 = wr[6], w1 = wr[7];
            a3 = d0.x*w0.x; a3 = fmaf(d0.y,w0.y,a3); a3 = fmaf(d0.z,w0.z,a3); a3 = fmaf(d0.w,w0.w,a3);
            a3 = fmaf(d1.x,w1.x,a3); a3 = fmaf(d1.y,w1.y,a3); a3 = fmaf(d1.z,w1.z,a3); a3 = fmaf(d1.w,w1.w,a3);
        }
#pragma unroll
        for (int off = 16; off > 0; off >>= 1) {
            a0 += __shfl_xor_sync(0xffffffffu, a0, off);
            a1 += __shfl_xor_sync(0xffffffffu, a1, off);
            a2 += __shfl_xor_sync(0xffffffffu, a2, off);
            a3 += __shfl_xor_sync(0xffffffffu, a3, off);
        }
        if (lane == 0) {
            const int t = c * CHUNK + trow;
            float4 v;
            v.x = 0.5f * (a0 + bb0);
            v.y = 0.5f * (a1 + bb1);
            v.z =         a2 + bb2;
            v.w = 0.5f * (a3 + bb3);
            g_xg[t * BB + bidx] = v;
        }
        __syncthreads();
        if (tid == 0) rel_add(&g_cnt[c], 16);
    }
}

extern "C" void kernel_launch(void* const* d_in, const int* in_sizes, int n_in,
                              void* d_out, int out_size)
{
    const float* data = (const float*)d_in[0];
    const int*   seq  = (const int*)  d_in[1];
    const float* w_ih = (const float*)d_in[2];
    const float* w_hh = (const float*)d_in[3];
    const float* b_ih = (const float*)d_in[4];
    const float* b_hh = (const float*)d_in[5];
    float* out = (float*)d_out;

    int tail = out_size - BT;
    if (tail < 0) tail = 0;
    if (tail > BB) tail = BB;

    fused_kernel<<<NSEG + GATE_BLOCKS, TPB>>>(data, seq, w_ih, w_hh, b_ih, b_hh, out, tail);
}

// round 12
// speedup vs baseline: 2.8614x; 1.0040x over previous
#include <cuda_runtime.h>
#include <cuda_bf16.h>
#include <cstdint>

#define BB 64
#define TT 2048
#define EE 256
#define BT (BB*TT)
#define CHUNK 32
#define NCHUNK (TT/CHUNK)              // 64
#define NSEG 16                        // scan segments (blocks 0..15)
#define SEGLEN 128
#define GATE_BLOCKS 128
#define TPB 512
#define FULLCNT 2048                   // 128 blocks * 16 warps per chunk
#define PFDIST 12                      // L2 prefetch lookahead (chunks)

// xg time-major [T+pad][B] float4 (gates i,f,g,o; sigmoid gates pre-halved, bias folded)
__device__ __align__(16) float4 g_xg[(TT + 16) * BB];
// producer->scan per-chunk counters (reset by last-finishing poller)
__device__ __align__(16) int g_cnt[NCHUNK];
// poller completion rendezvous
__device__ int g_done;

__device__ __forceinline__ float tanha(float x) {
    float y; asm("tanh.approx.f32 %0, %1;" : "=f"(y) : "f"(x)); return y;
}
__device__ __forceinline__ int acq_ld(const int* p) {
    int v; asm volatile("ld.acquire.gpu.global.b32 %0, [%1];" : "=r"(v) : "l"(p) : "memory"); return v;
}
__device__ __forceinline__ void rel_add(int* p, int v) {
    asm volatile("red.release.gpu.global.add.s32 [%0], %1;" :: "l"(p), "r"(v) : "memory");
}
__device__ __forceinline__ int atom_aa(int* p, int v) {
    int o; asm volatile("atom.acq_rel.gpu.global.add.s32 %0, [%1], %2;"
                        : "=r"(o) : "l"(p), "r"(v) : "memory"); return o;
}
__device__ __forceinline__ void pf_l2(const void* p) {
    asm volatile("prefetch.global.L2 [%0];" :: "l"(p));
}
__device__ __forceinline__ float sigf(float h) {
    return fmaf(0.5f, tanha(0.5f * h), 0.5f);
}
// named barriers, 96 participants (3 warps). 1=XRDY, 2/3=HFULL(par), 4/5=HFREE(par)
#define BARS96(id) asm volatile("bar.sync %0, 96;"   :: "r"(id) : "memory")
#define BARA96(id) asm volatile("bar.arrive %0, 96;" :: "r"(id) : "memory")

__global__ __launch_bounds__(TPB, 1) void fused_kernel(
    const float* __restrict__ data,
    const int*   __restrict__ seq,
    const float* __restrict__ w_ih,
    const float* __restrict__ w_hh,
    const float* __restrict__ b_ih,
    const float* __restrict__ b_hh,
    float* __restrict__ out,
    int tail)
{
    const int tid  = threadIdx.x;
    const int warp = tid >> 5;
    const int lane = tid & 31;

    if (blockIdx.x < NSEG) {
        // ========== SCAN BLOCK for segment s: warm-up 128 + real 128 steps ==========
        const int s  = blockIdx.x;
        const int tw = (s == 0) ? 0 : s * SEGLEN - SEGLEN;   // first (warm) step
        const int nchunks = (s == 0) ? 4 : 8;
        const int warmch  = nchunks - 4;
        const int gk0 = tw >> 5;                             // first global chunk

        __shared__ float hbuf[2][BB][33];                    // [parity][chain][step]

        if (warp >= 4) return;

        if (warp == 2) {
            // ---------------- poller warp ----------------
            int ready = 0;
            for (int k = 0; k < nchunks; k++) {
                int need = gk0 + k + 2; if (need > NCHUNK) need = NCHUNK;
                while (ready < need) {
                    int far = ready + 6; if (far > NCHUNK-1) far = NCHUNK-1;
                    if (acq_ld(g_cnt + far) == FULLCNT)        ready = far + 1;
                    else if (acq_ld(g_cnt + ready) == FULLCNT) ready++;
                }
                BARS96(1);                                   // XRDY for chunk k
            }
            __syncwarp();
            if (lane == 0) {
                if (atom_aa(&g_done, 1) == NSEG - 1) {       // last poller: reset
#pragma unroll
                    for (int i = 0; i < NCHUNK; i++) g_cnt[i] = 0;
                    g_done = 0;
                }
            }
            return;
        }

        if (warp == 3) {
            // ---------------- consumer warp: sigmoid + mask + store ----------------
            for (int rc = 0; rc < 4; rc++) {
                const int p = rc & 1;
                BARS96(2 + p);                               // HFULL
                const int tcol = s * SEGLEN + rc * 32 + lane;
#pragma unroll 4
                for (int b = 0; b < BB; b++) {
                    float h = hbuf[p][b][lane];
                    int sq = __ldg(seq + b);
                    float v = (tcol < sq) ? sigf(h) : 0.5f;
                    out[(size_t)b * TT + tcol] = v;
                }
                if (rc < 2) BARA96(4 + p);                   // HFREE
            }
            if (s == 0) {                                    // tuple tail: seq as float
                if (lane      < tail) out[BT + lane]      = (float)__ldg(seq + lane);
                if (lane + 32 < tail) out[BT + lane + 32] = (float)__ldg(seq + lane + 32);
            }
            return;
        }

        // ---------------- scan warps 0,1: chains warp*32 + lane ----------------
        const int b = warp * 32 + lane;
        const float w0h = 0.5f * __ldg(w_hh+0);
        const float w1h = 0.5f * __ldg(w_hh+1);
        const float w2f =        __ldg(w_hh+2);
        const float w3h = 0.5f * __ldg(w_hh+3);

        const float4* xp = g_xg + b;                         // element t at xp[t*BB]

        float4 buf[8];
        float half_c = 0.f, h = 0.f;
        int t = tw;

        for (int k = 0; k < nchunks; k++) {
            BARS96(1);                                       // XRDY: chunks <= gk0+k+1 done
            if (k == 0) {
#pragma unroll
                for (int i = 0; i < 8; i++) buf[i] = __ldcg(xp + (tw + i) * BB);
            }
            const bool real = (k >= warmch);
            const int rc = k - warmch;
            const int p = rc & 1;
            if (real && rc >= 2) BARS96(4 + p);              // HFREE before reuse

#pragma unroll
            for (int u = 0; u < CHUNK; u++) {
                float4 x = buf[u & 7];
                buf[u & 7] = __ldcg(xp + (t + u + 8) * BB);  // padded: in bounds

                float g1 = fmaf(w1h, h, x.y);
                float t1 = tanha(g1);
                float g2 = fmaf(w2f, h, x.z);
                float tg = tanha(g2);
                float g0 = fmaf(w0h, h, x.x);
                float t0 = tanha(g0);
                float g3 = fmaf(w3h, h, x.w);
                float t3 = tanha(g3);

                float r  = fmaf(t1, half_c, half_c);         // f * c_prev
                float qq = fmaf(t0, tg, tg);                 // 2 i g
                float c  = fmaf(0.5f, qq, r);
                half_c   = 0.5f * c;
                float o  = fmaf(0.5f, t3, 0.5f);
                float tc = tanha(c);
                h = o * tc;

                if (real) hbuf[p][b][u] = h;
            }
            t += CHUNK;
            if (real) BARA96(2 + p);                         // HFULL
        }
        return;
    }

    // ================= GATE BLOCKS (NSEG .. NSEG+127) =================
    const int kb = blockIdx.x - NSEG;         // 0..127
    const int s  = kb * 16 + warp;            // 0..2047: task slot within each chunk
    const int bidx = s & 63;
    const int trow = s >> 6;                  // 0..31

    const float4* wv = reinterpret_cast<const float4*>(w_ih);
    float4 wr[8];
#pragma unroll
    for (int g = 0; g < 4; g++) {
        wr[2*g]   = __ldg(wv + g*64 + lane);
        wr[2*g+1] = __ldg(wv + g*64 + 32 + lane);
    }
    const float bb0 = __ldg(b_ih+0) + __ldg(b_hh+0);
    const float bb1 = __ldg(b_ih+1) + __ldg(b_hh+1);
    const float bb2 = __ldg(b_ih+2) + __ldg(b_hh+2);
    const float bb3 = __ldg(b_ih+3) + __ldg(b_hh+3);

    const float4* dpb = reinterpret_cast<const float4*>(data)
                      + ((size_t)bidx * TT + trow) * (EE/4);
    const int cstride = CHUNK * (EE/4);

    // prime the L2 with chunks [4, PFDIST): register ring covers [0,4)
#pragma unroll
    for (int pc = 4; pc < PFDIST; pc++) {
        pf_l2(dpb + pc * cstride + lane);
        pf_l2(dpb + pc * cstride + 32 + lane);
    }

    // depth-4 chunk prefetch pipeline (register ring; loads mostly L2 hits)
    float4 A0[4], A1[4];
#pragma unroll
    for (int p = 0; p < 4; p++) {
        A0[p] = __ldcs(dpb + p * cstride + lane);
        A1[p] = __ldcs(dpb + p * cstride + 32 + lane);
    }

#pragma unroll 4
    for (int c = 0; c < NCHUNK; c++) {
        const int slot = c & 3;
        float4 d0 = A0[slot], d1 = A1[slot];
        if (c + 4 < NCHUNK) {
            A0[slot] = __ldcs(dpb + (c + 4) * cstride + lane);
            A1[slot] = __ldcs(dpb + (c + 4) * cstride + 32 + lane);
        }
        if (c + PFDIST < NCHUNK) {
            // DRAM->L2 lookahead: keeps ~PFDIST chunks of MLP without registers
            pf_l2(dpb + (c + PFDIST) * cstride + lane);
            pf_l2(dpb + (c + PFDIST) * cstride + 32 + lane);
        }

        float a0, a1, a2, a3;
        {
            float4 w0 = wr[0], w1 = wr[1];
            a0 = d0.x*w0.x; a0 = fmaf(d0.y,w0.y,a0); a0 = fmaf(d0.z,w0.z,a0); a0 = fmaf(d0.w,w0.w,a0);
            a0 = fmaf(d1.x,w1.x,a0); a0 = fmaf(d1.y,w1.y,a0); a0 = fmaf(d1.z,w1.z,a0); a0 = fmaf(d1.w,w1.w,a0);
        }
        {
            float4 w0 = wr[2], w1 = wr[3];
            a1 = d0.x*w0.x; a1 = fmaf(d0.y,w0.y,a1); a1 = fmaf(d0.z,w0.z,a1); a1 = fmaf(d0.w,w0.w,a1);
            a1 = fmaf(d1.x,w1.x,a1); a1 = fmaf(d1.y,w1.y,a1); a1 = fmaf(d1.z,w1.z,a1); a1 = fmaf(d1.w,w1.w,a1);
        }
        {
            float4 w0 = wr[4], w1 = wr[5];
            a2 = d0.x*w0.x; a2 = fmaf(d0.y,w0.y,a2); a2 = fmaf(d0.z,w0.z,a2); a2 = fmaf(d0.w,w0.w,a2);
            a2 = fmaf(d1.x,w1.x,a2); a2 = fmaf(d1.y,w1.y,a2); a2 = fmaf(d1.z,w1.z,a2); a2 = fmaf(d1.w,w1.w,a2);
        }
        {
            float4 w0 = wr[6], w1 = wr[7];
            a3 = d0.x*w0.x; a3 = fmaf(d0.y,w0.y,a3); a3 = fmaf(d0.z,w0.z,a3); a3 = fmaf(d0.w,w0.w,a3);
            a3 = fmaf(d1.x,w1.x,a3); a3 = fmaf(d1.y,w1.y,a3); a3 = fmaf(d1.z,w1.z,a3); a3 = fmaf(d1.w,w1.w,a3);
        }
#pragma unroll
        for (int off = 16; off > 0; off >>= 1) {
            a0 += __shfl_xor_sync(0xffffffffu, a0, off);
            a1 += __shfl_xor_sync(0xffffffffu, a1, off);
            a2 += __shfl_xor_sync(0xffffffffu, a2, off);
            a3 += __shfl_xor_sync(0xffffffffu, a3, off);
        }
        if (lane == 0) {
            const int t = c * CHUNK + trow;
            float4 v;
            v.x = 0.5f * (a0 + bb0);
            v.y = 0.5f * (a1 + bb1);
            v.z =         a2 + bb2;
            v.w = 0.5f * (a3 + bb3);
            g_xg[t * BB + bidx] = v;
        }
        __syncthreads();
        if (tid == 0) rel_add(&g_cnt[c], 16);
    }
}

extern "C" void kernel_launch(void* const* d_in, const int* in_sizes, int n_in,
                              void* d_out, int out_size)
{
    const float* data = (const float*)d_in[0];
    const int*   seq  = (const int*)  d_in[1];
    const float* w_ih = (const float*)d_in[2];
    const float* w_hh = (const float*)d_in[3];
    const float* b_ih = (const float*)d_in[4];
    const float* b_hh = (const float*)d_in[5];
    float* out = (float*)d_out;

    int tail = out_size - BT;
    if (tail < 0) tail = 0;
    if (tail > BB) tail = BB;

    fused_kernel<<<NSEG + GATE_BLOCKS, TPB>>>(data, seq, w_ih, w_hh, b_ih, b_hh, out, tail);
}